// round 1
// baseline (speedup 1.0000x reference)
#include <cuda_runtime.h>
#include <cuda_bf16.h>

// Problem constants (fixed by reference)
#define BB   32
#define NBX  6
#define HH   512
#define WW   512
#define PNp  512          // patch is PNp x PNp x 3
#define SCALE_F  0.5f
#define ASPECT_F 1.0f
#define MIN_PH_F 60.0f

struct __align__(16) PBox {
    int   y0, x0, h, w;     // truncated int box
    float inv_h, inv_w;     // PNp / max(h,1), PNp / max(w,1)
    int   valid;
    int   pad;
};

__device__ PBox g_pboxes[BB * NBX];

// ---------------------------------------------------------------------------
// Setup: derive per-(b,n) patch boxes exactly as the reference does.
// ---------------------------------------------------------------------------
__global__ void setup_boxes_kernel(const float* __restrict__ boxes) {
    int i = blockIdx.x * blockDim.x + threadIdx.x;
    if (i >= BB * NBX) return;
    const float* bx = boxes + (size_t)i * 4;
    float ymin = bx[0], xmin = bx[1], ymax = bx[2], xmax = bx[3];
    float h = ymax - ymin;
    float w = xmax - xmin;
    float pw = h * SCALE_F;
    float ph = ASPECT_F * pw;
    float oy = ymin + h * 0.5f;
    float ox = xmin + w * 0.5f;
    float yp = fmaxf(oy - ph * 0.5f, 0.0f);
    float xp = fmaxf(ox - pw * 0.5f, 0.0f);
    if (yp + ph > (float)HH) yp = (float)HH - ph;
    if (xp + pw > (float)WW) xp = (float)WW - pw;

    PBox pb;
    pb.y0 = (int)yp;            // truncation, values are non-negative
    pb.x0 = (int)xp;
    pb.h  = (int)ph;
    pb.w  = (int)pw;
    float hf = fmaxf((float)pb.h, 1.0f);
    float wf = fmaxf((float)pb.w, 1.0f);
    pb.inv_h = (float)PNp / hf;
    pb.inv_w = (float)PNp / wf;
    pb.valid = (ph > MIN_PH_F) ? 1 : 0;
    pb.pad = 0;
    g_pboxes[i] = pb;
}

// ---------------------------------------------------------------------------
// Main: one thread per 4 consecutive pixels (12 floats = 3 aligned float4).
// For each pixel, highest-n valid covering patch wins; else copy the image.
// ---------------------------------------------------------------------------
__global__ void __launch_bounds__(256)
paste_kernel(const float* __restrict__ img,
             const float* __restrict__ patch,
             float* __restrict__ out) {
    int t = blockIdx.x * blockDim.x + threadIdx.x;
    const int total = BB * HH * WW / 4;
    if (t >= total) return;

    int p0  = t << 2;                  // first pixel index of this group
    int b   = p0 >> 18;                // H*W = 2^18
    int rem = p0 & ((1 << 18) - 1);
    int y   = rem >> 9;                // W = 2^9
    int x   = rem & (WW - 1);          // group is within one row (W % 4 == 0)

    // Find topmost covering box per pixel
    int cov[4] = {-1, -1, -1, -1};
    #pragma unroll
    for (int n = NBX - 1; n >= 0; --n) {
        PBox pb = g_pboxes[b * NBX + n];
        if (!pb.valid) continue;
        int dy = y - pb.y0;
        if ((unsigned)dy >= (unsigned)pb.h) continue;
        int dx0 = x - pb.x0;
        #pragma unroll
        for (int k = 0; k < 4; ++k) {
            if (cov[k] < 0 && (unsigned)(dx0 + k) < (unsigned)pb.w) cov[k] = n;
        }
    }

    float px[4][3];
    bool allcov = (cov[0] >= 0) & (cov[1] >= 0) & (cov[2] >= 0) & (cov[3] >= 0);

    const float* ibase = img + (size_t)p0 * 3;
    if (!allcov) {
        float4 v0 = __ldg((const float4*)(ibase + 0));
        float4 v1 = __ldg((const float4*)(ibase + 4));
        float4 v2 = __ldg((const float4*)(ibase + 8));
        px[0][0] = v0.x; px[0][1] = v0.y; px[0][2] = v0.z;
        px[1][0] = v0.w; px[1][1] = v1.x; px[1][2] = v1.y;
        px[2][0] = v1.z; px[2][1] = v1.w; px[2][2] = v2.x;
        px[3][0] = v2.y; px[3][1] = v2.z; px[3][2] = v2.w;
    }

    #pragma unroll
    for (int k = 0; k < 4; ++k) {
        if (cov[k] < 0) continue;
        PBox pb = g_pboxes[b * NBX + cov[k]];
        int dy = y - pb.y0;
        int dx = (x + k) - pb.x0;

        float sy = ((float)dy + 0.5f) * pb.inv_h - 0.5f;
        float sx = ((float)dx + 0.5f) * pb.inv_w - 0.5f;
        sy = fminf(fmaxf(sy, 0.0f), (float)(PNp - 1));
        sx = fminf(fmaxf(sx, 0.0f), (float)(PNp - 1));

        int   yl = (int)floorf(sy);
        int   xl = (int)floorf(sx);
        float wy = sy - (float)yl;
        float wx = sx - (float)xl;
        int   yh = min(yl + 1, PNp - 1);
        int   xh = min(xl + 1, PNp - 1);

        const float* p00 = patch + ((size_t)yl * PNp + xl) * 3;
        const float* p01 = patch + ((size_t)yl * PNp + xh) * 3;
        const float* p10 = patch + ((size_t)yh * PNp + xl) * 3;
        const float* p11 = patch + ((size_t)yh * PNp + xh) * 3;

        float omwy = 1.0f - wy;
        float omwx = 1.0f - wx;
        #pragma unroll
        for (int c = 0; c < 3; ++c) {
            float rl = __ldg(p00 + c) * omwy + __ldg(p10 + c) * wy;  // col xl
            float rh = __ldg(p01 + c) * omwy + __ldg(p11 + c) * wy;  // col xh
            px[k][c] = rl * omwx + rh * wx;
        }
    }

    float4 o0, o1, o2;
    o0.x = px[0][0]; o0.y = px[0][1]; o0.z = px[0][2]; o0.w = px[1][0];
    o1.x = px[1][1]; o1.y = px[1][2]; o1.z = px[2][0]; o1.w = px[2][1];
    o2.x = px[2][2]; o2.y = px[3][0]; o2.z = px[3][1]; o2.w = px[3][2];

    float* obase = out + (size_t)p0 * 3;
    *(float4*)(obase + 0) = o0;
    *(float4*)(obase + 4) = o1;
    *(float4*)(obase + 8) = o2;
}

extern "C" void kernel_launch(void* const* d_in, const int* in_sizes, int n_in,
                              void* d_out, int out_size) {
    const float* images = (const float*)d_in[0];   // [32,512,512,3] f32
    const float* boxes  = (const float*)d_in[1];   // [32,6,4] f32
    const float* patch  = (const float*)d_in[2];   // [512,512,3] f32
    float* out = (float*)d_out;

    setup_boxes_kernel<<<1, 256>>>(boxes);

    const int total = BB * HH * WW / 4;            // 2,097,152 threads
    paste_kernel<<<total / 256, 256>>>(images, patch, out);
}

// round 2
// speedup vs baseline: 1.1021x; 1.1021x over previous
#include <cuda_runtime.h>
#include <cuda_bf16.h>

// Problem constants (fixed by reference)
#define BB   32
#define NBX  6
#define HH   512
#define WW   512
#define PNp  512          // patch is PNp x PNp x 3
#define SCALE_F  0.5f
#define ASPECT_F 1.0f
#define MIN_PH_F 60.0f

struct __align__(16) PBox {
    int   y0, x0, h, w;     // truncated int box
    float inv_h, inv_w;     // PNp / max(h,1), PNp / max(w,1)
    int   valid;
    int   pad;
};

__device__ PBox   g_pboxes[BB * NBX];
__device__ float4 g_patch4[PNp * PNp];   // RGBx re-layout of the patch (4 MB)

// ---------------------------------------------------------------------------
// Setup: derive per-(b,n) patch boxes exactly as the reference does.
// ---------------------------------------------------------------------------
__global__ void setup_boxes_kernel(const float* __restrict__ boxes) {
    int i = blockIdx.x * blockDim.x + threadIdx.x;
    if (i >= BB * NBX) return;
    const float* bx = boxes + (size_t)i * 4;
    float ymin = bx[0], xmin = bx[1], ymax = bx[2], xmax = bx[3];
    float h = ymax - ymin;
    float w = xmax - xmin;
    float pw = h * SCALE_F;
    float ph = ASPECT_F * pw;
    float oy = ymin + h * 0.5f;
    float ox = xmin + w * 0.5f;
    float yp = fmaxf(oy - ph * 0.5f, 0.0f);
    float xp = fmaxf(ox - pw * 0.5f, 0.0f);
    if (yp + ph > (float)HH) yp = (float)HH - ph;
    if (xp + pw > (float)WW) xp = (float)WW - pw;

    PBox pb;
    pb.y0 = (int)yp;
    pb.x0 = (int)xp;
    pb.h  = (int)ph;
    pb.w  = (int)pw;
    float hf = fmaxf((float)pb.h, 1.0f);
    float wf = fmaxf((float)pb.w, 1.0f);
    pb.inv_h = (float)PNp / hf;
    pb.inv_w = (float)PNp / wf;
    pb.valid = (ph > MIN_PH_F) ? 1 : 0;
    pb.pad = 0;
    g_pboxes[i] = pb;
}

// ---------------------------------------------------------------------------
// Prep: convert patch [512,512,3] f32 -> float4 RGBx for single-load texels.
// ---------------------------------------------------------------------------
__global__ void __launch_bounds__(256)
prep_patch_kernel(const float* __restrict__ patch) {
    int i = blockIdx.x * blockDim.x + threadIdx.x;
    if (i >= PNp * PNp) return;
    const float* p = patch + (size_t)i * 3;
    float4 v;
    v.x = __ldg(p + 0);
    v.y = __ldg(p + 1);
    v.z = __ldg(p + 2);
    v.w = 0.0f;
    g_patch4[i] = v;
}

// ---------------------------------------------------------------------------
// Main: one thread per 4 consecutive pixels (12 floats = 3 aligned float4).
// Each block covers 1024 contiguous pixels of ONE image -> boxes in smem.
// ---------------------------------------------------------------------------
__global__ void __launch_bounds__(256)
paste_kernel(const float* __restrict__ img,
             float* __restrict__ out) {
    __shared__ PBox sbox[NBX];
    {
        // copy 6 PBoxes (48 ints) with the first 48 threads
        const int* src = (const int*)(g_pboxes + (blockIdx.x >> 8) * NBX);
        int* dst = (int*)sbox;
        if (threadIdx.x < NBX * 8) dst[threadIdx.x] = src[threadIdx.x];
    }
    __syncthreads();

    int t  = blockIdx.x * blockDim.x + threadIdx.x;
    int p0 = t << 2;                   // first pixel index of this group
    int rem = p0 & ((1 << 18) - 1);    // within-image index
    int y   = rem >> 9;                // W = 2^9
    int x   = rem & (WW - 1);

    // Find topmost covering box per pixel
    int cov[4] = {-1, -1, -1, -1};
    #pragma unroll
    for (int n = NBX - 1; n >= 0; --n) {
        PBox pb = sbox[n];
        if (!pb.valid) continue;
        int dy = y - pb.y0;
        if ((unsigned)dy >= (unsigned)pb.h) continue;
        int dx0 = x - pb.x0;
        #pragma unroll
        for (int k = 0; k < 4; ++k) {
            if (cov[k] < 0 && (unsigned)(dx0 + k) < (unsigned)pb.w) cov[k] = n;
        }
    }

    float px[4][3];
    bool allcov = (cov[0] >= 0) & (cov[1] >= 0) & (cov[2] >= 0) & (cov[3] >= 0);

    const float* ibase = img + (size_t)p0 * 3;
    if (!allcov) {
        float4 v0 = __ldg((const float4*)(ibase + 0));
        float4 v1 = __ldg((const float4*)(ibase + 4));
        float4 v2 = __ldg((const float4*)(ibase + 8));
        px[0][0] = v0.x; px[0][1] = v0.y; px[0][2] = v0.z;
        px[1][0] = v0.w; px[1][1] = v1.x; px[1][2] = v1.y;
        px[2][0] = v1.z; px[2][1] = v1.w; px[2][2] = v2.x;
        px[3][0] = v2.y; px[3][1] = v2.z; px[3][2] = v2.w;
    }

    #pragma unroll
    for (int k = 0; k < 4; ++k) {
        if (cov[k] < 0) continue;
        PBox pb = sbox[cov[k]];
        int dy = y - pb.y0;
        int dx = (x + k) - pb.x0;

        float sy = ((float)dy + 0.5f) * pb.inv_h - 0.5f;
        float sx = ((float)dx + 0.5f) * pb.inv_w - 0.5f;
        sy = fminf(fmaxf(sy, 0.0f), (float)(PNp - 1));
        sx = fminf(fmaxf(sx, 0.0f), (float)(PNp - 1));

        int   yl = (int)floorf(sy);
        int   xl = (int)floorf(sx);
        float wy = sy - (float)yl;
        float wx = sx - (float)xl;
        int   yh = min(yl + 1, PNp - 1);
        int   xh = min(xl + 1, PNp - 1);

        float4 t00 = __ldg(&g_patch4[yl * PNp + xl]);
        float4 t01 = __ldg(&g_patch4[yl * PNp + xh]);
        float4 t10 = __ldg(&g_patch4[yh * PNp + xl]);
        float4 t11 = __ldg(&g_patch4[yh * PNp + xh]);

        float omwy = 1.0f - wy;
        float omwx = 1.0f - wx;
        // rows = patch[yl]*(1-wy) + patch[yh]*wy ; val = rl*(1-wx) + rh*wx
        float rlx = t00.x * omwy + t10.x * wy;
        float rly = t00.y * omwy + t10.y * wy;
        float rlz = t00.z * omwy + t10.z * wy;
        float rhx = t01.x * omwy + t11.x * wy;
        float rhy = t01.y * omwy + t11.y * wy;
        float rhz = t01.z * omwy + t11.z * wy;
        px[k][0] = rlx * omwx + rhx * wx;
        px[k][1] = rly * omwx + rhy * wx;
        px[k][2] = rlz * omwx + rhz * wx;
    }

    float4 o0, o1, o2;
    o0.x = px[0][0]; o0.y = px[0][1]; o0.z = px[0][2]; o0.w = px[1][0];
    o1.x = px[1][1]; o1.y = px[1][2]; o1.z = px[2][0]; o1.w = px[2][1];
    o2.x = px[2][2]; o2.y = px[3][0]; o2.z = px[3][1]; o2.w = px[3][2];

    float* obase = out + (size_t)p0 * 3;
    *(float4*)(obase + 0) = o0;
    *(float4*)(obase + 4) = o1;
    *(float4*)(obase + 8) = o2;
}

extern "C" void kernel_launch(void* const* d_in, const int* in_sizes, int n_in,
                              void* d_out, int out_size) {
    const float* images = (const float*)d_in[0];   // [32,512,512,3] f32
    const float* boxes  = (const float*)d_in[1];   // [32,6,4] f32
    const float* patch  = (const float*)d_in[2];   // [512,512,3] f32
    float* out = (float*)d_out;

    setup_boxes_kernel<<<1, 256>>>(boxes);
    prep_patch_kernel<<<(PNp * PNp) / 256, 256>>>(patch);

    const int total = BB * HH * WW / 4;            // 2,097,152 threads
    paste_kernel<<<total / 256, 256>>>(images, out);
}

// round 4
// speedup vs baseline: 1.3351x; 1.2113x over previous
#include <cuda_runtime.h>
#include <cuda_bf16.h>

// Problem constants (fixed by reference)
#define BB   32
#define NBX  6
#define HH   512
#define WW   512
#define PNp  512          // patch is PNp x PNp x 3
#define SCALE_F  0.5f
#define ASPECT_F 1.0f
#define MIN_PH_F 60.0f

struct __align__(16) PBox {
    int   y0, x0, h, w;
    float inv_h, inv_w;
    int   valid;
    int   pad;
};

// y-pair packed patch: 32 bytes per (y,x):
//   [0..2] = patch[y][x].rgb, [3] = 0, [4..6] = patch[min(y+1,511)][x].rgb, [7] = 0
struct __align__(32) TexPair { float v[8]; };
__device__ TexPair g_pair[PNp * PNp];    // 8 MB

// ---------------------------------------------------------------------------
// Prep: build the y-pair packed patch.
// ---------------------------------------------------------------------------
__global__ void __launch_bounds__(256)
prep_patch_kernel(const float* __restrict__ patch) {
    int i = blockIdx.x * blockDim.x + threadIdx.x;   // i = y*512 + x
    if (i >= PNp * PNp) return;
    int y  = i >> 9;
    int yh = min(y + 1, PNp - 1);
    int x  = i & (PNp - 1);
    const float* p0 = patch + ((size_t)y  * PNp + x) * 3;
    const float* p1 = patch + ((size_t)yh * PNp + x) * 3;
    TexPair t;
    t.v[0] = __ldg(p0 + 0); t.v[1] = __ldg(p0 + 1); t.v[2] = __ldg(p0 + 2); t.v[3] = 0.0f;
    t.v[4] = __ldg(p1 + 0); t.v[5] = __ldg(p1 + 1); t.v[6] = __ldg(p1 + 2); t.v[7] = 0.0f;
    g_pair[i] = t;
}

// 256-bit global load (sm_100+): 8 consecutive floats, 32B-aligned.
__device__ __forceinline__ void ldg256(const TexPair* p, float r[8]) {
    asm volatile("ld.global.nc.v8.f32 {%0,%1,%2,%3,%4,%5,%6,%7}, [%8];"
                 : "=f"(r[0]), "=f"(r[1]), "=f"(r[2]), "=f"(r[3]),
                   "=f"(r[4]), "=f"(r[5]), "=f"(r[6]), "=f"(r[7])
                 : "l"(p));
}

// ---------------------------------------------------------------------------
// Main: one thread per 4 consecutive pixels (12 floats = 3 aligned float4).
// Each block covers 1024 contiguous pixels of ONE image. Boxes computed
// in-block from the raw boxes input (no setup kernel).
// ---------------------------------------------------------------------------
__global__ void __launch_bounds__(256)
paste_kernel(const float* __restrict__ img,
             const float* __restrict__ boxes,
             float* __restrict__ out) {
    __shared__ PBox sbox[NBX];
    int b = blockIdx.x >> 8;           // 256 blocks per image
    if (threadIdx.x < NBX) {
        const float* bx = boxes + ((size_t)b * NBX + threadIdx.x) * 4;
        float ymin = __ldg(bx + 0), xmin = __ldg(bx + 1);
        float ymax = __ldg(bx + 2), xmax = __ldg(bx + 3);
        float h = ymax - ymin;
        float w = xmax - xmin;
        float pw = h * SCALE_F;
        float ph = ASPECT_F * pw;
        float oy = ymin + h * 0.5f;
        float ox = xmin + w * 0.5f;
        float yp = fmaxf(oy - ph * 0.5f, 0.0f);
        float xp = fmaxf(ox - pw * 0.5f, 0.0f);
        if (yp + ph > (float)HH) yp = (float)HH - ph;
        if (xp + pw > (float)WW) xp = (float)WW - pw;
        PBox pb;
        pb.y0 = (int)yp;
        pb.x0 = (int)xp;
        pb.h  = (int)ph;
        pb.w  = (int)pw;
        pb.inv_h = (float)PNp / fmaxf((float)pb.h, 1.0f);
        pb.inv_w = (float)PNp / fmaxf((float)pb.w, 1.0f);
        pb.valid = (ph > MIN_PH_F) ? 1 : 0;
        pb.pad = 0;
        sbox[threadIdx.x] = pb;
    }
    __syncthreads();

    int t  = blockIdx.x * blockDim.x + threadIdx.x;
    int p0 = t << 2;                   // first pixel index of this group
    int rem = p0 & ((1 << 18) - 1);    // within-image index
    int y   = rem >> 9;                // W = 2^9
    int x   = rem & (WW - 1);

    // Find topmost covering box per pixel
    int cov[4] = {-1, -1, -1, -1};
    #pragma unroll
    for (int n = NBX - 1; n >= 0; --n) {
        PBox pb = sbox[n];
        if (!pb.valid) continue;
        int dy = y - pb.y0;
        if ((unsigned)dy >= (unsigned)pb.h) continue;
        int dx0 = x - pb.x0;
        #pragma unroll
        for (int k = 0; k < 4; ++k) {
            if (cov[k] < 0 && (unsigned)(dx0 + k) < (unsigned)pb.w) cov[k] = n;
        }
    }

    float px[4][3];
    bool allcov = (cov[0] >= 0) & (cov[1] >= 0) & (cov[2] >= 0) & (cov[3] >= 0);

    const float* ibase = img + (size_t)p0 * 3;
    if (!allcov) {
        float4 v0 = __ldg((const float4*)(ibase + 0));
        float4 v1 = __ldg((const float4*)(ibase + 4));
        float4 v2 = __ldg((const float4*)(ibase + 8));
        px[0][0] = v0.x; px[0][1] = v0.y; px[0][2] = v0.z;
        px[1][0] = v0.w; px[1][1] = v1.x; px[1][2] = v1.y;
        px[2][0] = v1.z; px[2][1] = v1.w; px[2][2] = v2.x;
        px[3][0] = v2.y; px[3][1] = v2.z; px[3][2] = v2.w;
    }

    #pragma unroll
    for (int k = 0; k < 4; ++k) {
        if (cov[k] < 0) continue;
        PBox pb = sbox[cov[k]];
        int dy = y - pb.y0;
        int dx = (x + k) - pb.x0;

        float sy = ((float)dy + 0.5f) * pb.inv_h - 0.5f;
        float sx = ((float)dx + 0.5f) * pb.inv_w - 0.5f;
        sy = fminf(fmaxf(sy, 0.0f), (float)(PNp - 1));
        sx = fminf(fmaxf(sx, 0.0f), (float)(PNp - 1));

        int   yl = (int)floorf(sy);
        int   xl = (int)floorf(sx);
        float wy = sy - (float)yl;
        float wx = sx - (float)xl;
        int   xh = min(xl + 1, PNp - 1);

        float a[8], c[8];
        ldg256(&g_pair[yl * PNp + xl], a);   // t00 (lo), t10 (hi)
        ldg256(&g_pair[yl * PNp + xh], c);   // t01 (lo), t11 (hi)

        float omwy = 1.0f - wy;
        float omwx = 1.0f - wx;
        float rlx = a[0] * omwy + a[4] * wy;
        float rly = a[1] * omwy + a[5] * wy;
        float rlz = a[2] * omwy + a[6] * wy;
        float rhx = c[0] * omwy + c[4] * wy;
        float rhy = c[1] * omwy + c[5] * wy;
        float rhz = c[2] * omwy + c[6] * wy;
        px[k][0] = rlx * omwx + rhx * wx;
        px[k][1] = rly * omwx + rhy * wx;
        px[k][2] = rlz * omwx + rhz * wx;
    }

    float4 o0, o1, o2;
    o0.x = px[0][0]; o0.y = px[0][1]; o0.z = px[0][2]; o0.w = px[1][0];
    o1.x = px[1][1]; o1.y = px[1][2]; o1.z = px[2][0]; o1.w = px[2][1];
    o2.x = px[2][2]; o2.y = px[3][0]; o2.z = px[3][1]; o2.w = px[3][2];

    float* obase = out + (size_t)p0 * 3;
    *(float4*)(obase + 0) = o0;
    *(float4*)(obase + 4) = o1;
    *(float4*)(obase + 8) = o2;
}

extern "C" void kernel_launch(void* const* d_in, const int* in_sizes, int n_in,
                              void* d_out, int out_size) {
    const float* images = (const float*)d_in[0];   // [32,512,512,3] f32
    const float* boxes  = (const float*)d_in[1];   // [32,6,4] f32
    const float* patch  = (const float*)d_in[2];   // [512,512,3] f32
    float* out = (float*)d_out;

    prep_patch_kernel<<<(PNp * PNp) / 256, 256>>>(patch);

    const int total = BB * HH * WW / 4;            // 2,097,152 threads
    paste_kernel<<<total / 256, 256>>>(images, boxes, out);
}

// round 5
// speedup vs baseline: 1.5135x; 1.1337x over previous
#include <cuda_runtime.h>
#include <cuda_fp16.h>

// Problem constants (fixed by reference)
#define BB   32
#define NBX  6
#define HH   512
#define WW   512
#define PNp  512          // patch is PNp x PNp x 3
#define SCALE_F  0.5f
#define ASPECT_F 1.0f
#define MIN_PH_F 60.0f

struct __align__(16) PBox {
    int   y0, x0, h, w;
    float inv_h, inv_w;
    int   valid;
    int   pad;
};

// fp16 y-pair packed patch texel: 16 bytes per (y,x):
//   h[0..2] = patch[y][x].rgb, h[3] = 0, h[4..6] = patch[min(y+1,511)][x].rgb, h[7] = 0
__device__ uint4 g_pairh[PNp * PNp];     // 4 MB

// ---------------------------------------------------------------------------
// Prep: build fp16 y-pair packed patch.
// ---------------------------------------------------------------------------
__global__ void __launch_bounds__(256)
prep_patch_kernel(const float* __restrict__ patch) {
    int i = blockIdx.x * blockDim.x + threadIdx.x;   // i = y*512 + x
    if (i >= PNp * PNp) return;
    int y  = i >> 9;
    int yh = min(y + 1, PNp - 1);
    int x  = i & (PNp - 1);
    const float* p0 = patch + ((size_t)y  * PNp + x) * 3;
    const float* p1 = patch + ((size_t)yh * PNp + x) * 3;

    __half2 h01 = __floats2half2_rn(__ldg(p0 + 0), __ldg(p0 + 1)); // r0,g0
    __half2 h23 = __floats2half2_rn(__ldg(p0 + 2), 0.0f);          // b0,-
    __half2 h45 = __floats2half2_rn(__ldg(p1 + 0), __ldg(p1 + 1)); // r1,g1
    __half2 h67 = __floats2half2_rn(__ldg(p1 + 2), 0.0f);          // b1,-

    uint4 u;
    u.x = *(const unsigned*)&h01;
    u.y = *(const unsigned*)&h23;
    u.z = *(const unsigned*)&h45;
    u.w = *(const unsigned*)&h67;
    g_pairh[i] = u;
}

// ---------------------------------------------------------------------------
// Main: one thread per 4 consecutive pixels (12 floats = 3 aligned float4).
// Each block covers 1024 contiguous pixels of ONE image. Boxes computed
// in-block from the raw boxes input.
// ---------------------------------------------------------------------------
__global__ void __launch_bounds__(256)
paste_kernel(const float* __restrict__ img,
             const float* __restrict__ boxes,
             float* __restrict__ out) {
    __shared__ PBox sbox[NBX];
    int b = blockIdx.x >> 8;           // 256 blocks per image
    if (threadIdx.x < NBX) {
        const float* bx = boxes + ((size_t)b * NBX + threadIdx.x) * 4;
        float ymin = __ldg(bx + 0), xmin = __ldg(bx + 1);
        float ymax = __ldg(bx + 2), xmax = __ldg(bx + 3);
        float h = ymax - ymin;
        float w = xmax - xmin;
        float pw = h * SCALE_F;
        float ph = ASPECT_F * pw;
        float oy = ymin + h * 0.5f;
        float ox = xmin + w * 0.5f;
        float yp = fmaxf(oy - ph * 0.5f, 0.0f);
        float xp = fmaxf(ox - pw * 0.5f, 0.0f);
        if (yp + ph > (float)HH) yp = (float)HH - ph;
        if (xp + pw > (float)WW) xp = (float)WW - pw;
        PBox pb;
        pb.y0 = (int)yp;
        pb.x0 = (int)xp;
        pb.h  = (int)ph;
        pb.w  = (int)pw;
        pb.inv_h = (float)PNp / fmaxf((float)pb.h, 1.0f);
        pb.inv_w = (float)PNp / fmaxf((float)pb.w, 1.0f);
        pb.valid = (ph > MIN_PH_F) ? 1 : 0;
        pb.pad = 0;
        sbox[threadIdx.x] = pb;
    }
    __syncthreads();

    int t  = blockIdx.x * blockDim.x + threadIdx.x;
    int p0 = t << 2;                   // first pixel index of this group
    int rem = p0 & ((1 << 18) - 1);    // within-image index
    int y   = rem >> 9;                // W = 2^9
    int x   = rem & (WW - 1);

    // Find topmost covering box per pixel
    int cov[4] = {-1, -1, -1, -1};
    #pragma unroll
    for (int n = NBX - 1; n >= 0; --n) {
        PBox pb = sbox[n];
        if (!pb.valid) continue;
        int dy = y - pb.y0;
        if ((unsigned)dy >= (unsigned)pb.h) continue;
        int dx0 = x - pb.x0;
        #pragma unroll
        for (int k = 0; k < 4; ++k) {
            if (cov[k] < 0 && (unsigned)(dx0 + k) < (unsigned)pb.w) cov[k] = n;
        }
    }

    float px[4][3];
    bool allcov = (cov[0] >= 0) & (cov[1] >= 0) & (cov[2] >= 0) & (cov[3] >= 0);

    const float* ibase = img + (size_t)p0 * 3;
    if (!allcov) {
        float4 v0 = __ldcs((const float4*)(ibase + 0));
        float4 v1 = __ldcs((const float4*)(ibase + 4));
        float4 v2 = __ldcs((const float4*)(ibase + 8));
        px[0][0] = v0.x; px[0][1] = v0.y; px[0][2] = v0.z;
        px[1][0] = v0.w; px[1][1] = v1.x; px[1][2] = v1.y;
        px[2][0] = v1.z; px[2][1] = v1.w; px[2][2] = v2.x;
        px[3][0] = v2.y; px[3][1] = v2.z; px[3][2] = v2.w;
    }

    #pragma unroll
    for (int k = 0; k < 4; ++k) {
        if (cov[k] < 0) continue;
        PBox pb = sbox[cov[k]];
        int dy = y - pb.y0;
        int dx = (x + k) - pb.x0;

        float sy = ((float)dy + 0.5f) * pb.inv_h - 0.5f;
        float sx = ((float)dx + 0.5f) * pb.inv_w - 0.5f;
        sy = fminf(fmaxf(sy, 0.0f), (float)(PNp - 1));
        sx = fminf(fmaxf(sx, 0.0f), (float)(PNp - 1));

        int   yl = (int)floorf(sy);
        int   xl = (int)floorf(sx);
        float wy = sy - (float)yl;
        float wx = sx - (float)xl;
        int   xh = min(xl + 1, PNp - 1);

        uint4 ua = __ldg(&g_pairh[yl * PNp + xl]);   // t00 (lo), t10 (hi)
        uint4 uc = __ldg(&g_pairh[yl * PNp + xh]);   // t01 (lo), t11 (hi)

        float2 a01 = __half22float2(*(const __half2*)&ua.x); // r0,g0
        float2 a23 = __half22float2(*(const __half2*)&ua.y); // b0,-
        float2 a45 = __half22float2(*(const __half2*)&ua.z); // r1,g1
        float2 a67 = __half22float2(*(const __half2*)&ua.w); // b1,-
        float2 c01 = __half22float2(*(const __half2*)&uc.x);
        float2 c23 = __half22float2(*(const __half2*)&uc.y);
        float2 c45 = __half22float2(*(const __half2*)&uc.z);
        float2 c67 = __half22float2(*(const __half2*)&uc.w);

        float omwy = 1.0f - wy;
        float omwx = 1.0f - wx;
        float rlx = a01.x * omwy + a45.x * wy;
        float rly = a01.y * omwy + a45.y * wy;
        float rlz = a23.x * omwy + a67.x * wy;
        float rhx = c01.x * omwy + c45.x * wy;
        float rhy = c01.y * omwy + c45.y * wy;
        float rhz = c23.x * omwy + c67.x * wy;
        px[k][0] = rlx * omwx + rhx * wx;
        px[k][1] = rly * omwx + rhy * wx;
        px[k][2] = rlz * omwx + rhz * wx;
    }

    float4 o0, o1, o2;
    o0.x = px[0][0]; o0.y = px[0][1]; o0.z = px[0][2]; o0.w = px[1][0];
    o1.x = px[1][1]; o1.y = px[1][2]; o1.z = px[2][0]; o1.w = px[2][1];
    o2.x = px[2][2]; o2.y = px[3][0]; o2.z = px[3][1]; o2.w = px[3][2];

    float* obase = out + (size_t)p0 * 3;
    __stcs((float4*)(obase + 0), o0);
    __stcs((float4*)(obase + 4), o1);
    __stcs((float4*)(obase + 8), o2);
}

extern "C" void kernel_launch(void* const* d_in, const int* in_sizes, int n_in,
                              void* d_out, int out_size) {
    const float* images = (const float*)d_in[0];   // [32,512,512,3] f32
    const float* boxes  = (const float*)d_in[1];   // [32,6,4] f32
    const float* patch  = (const float*)d_in[2];   // [512,512,3] f32
    float* out = (float*)d_out;

    prep_patch_kernel<<<(PNp * PNp) / 256, 256>>>(patch);

    const int total = BB * HH * WW / 4;            // 2,097,152 threads
    paste_kernel<<<total / 256, 256>>>(images, boxes, out);
}

// round 6
// speedup vs baseline: 1.5394x; 1.0171x over previous
#include <cuda_runtime.h>
#include <cuda_fp16.h>

// Problem constants (fixed by reference)
#define BB   32
#define NBX  6
#define HH   512
#define WW   512
#define PNp  512          // patch is PNp x PNp x 3
#define SCALE_F  0.5f
#define ASPECT_F 1.0f
#define MIN_PH_F 60.0f

struct __align__(16) PBox {
    int   y0, x0, h, w;
    float inv_h, inv_w;
    int   valid;
    int   pad;
};

// Quad-packed patch texel: for each (y,x), the full 2x2 bilinear footprint
// with clamped neighbors yh=min(y+1,511), xh=min(x+1,511), as fp16:
//   h2[0]=(r00,r01) h2[1]=(g00,g01) h2[2]=(b00,b01)
//   h2[3]=(r10,r11) h2[4]=(g10,g11) h2[5]=(b10,b11)  h2[6..7]=pad
// 32 bytes per entry -> one 256-bit load per covered pixel.
struct __align__(32) Quad { unsigned u[8]; };
__device__ Quad g_quad[PNp * PNp];       // 8 MB

// ---------------------------------------------------------------------------
// Prep: build quad-packed fp16 patch.
// ---------------------------------------------------------------------------
__global__ void __launch_bounds__(256)
prep_patch_kernel(const float* __restrict__ patch) {
    int i = blockIdx.x * blockDim.x + threadIdx.x;   // i = y*512 + x
    if (i >= PNp * PNp) return;
    int y  = i >> 9;
    int x  = i & (PNp - 1);
    int yh = min(y + 1, PNp - 1);
    int xh = min(x + 1, PNp - 1);

    const float* p00 = patch + ((size_t)y  * PNp + x ) * 3;
    const float* p01 = patch + ((size_t)y  * PNp + xh) * 3;
    const float* p10 = patch + ((size_t)yh * PNp + x ) * 3;
    const float* p11 = patch + ((size_t)yh * PNp + xh) * 3;

    __half2 r0 = __floats2half2_rn(__ldg(p00 + 0), __ldg(p01 + 0));
    __half2 g0 = __floats2half2_rn(__ldg(p00 + 1), __ldg(p01 + 1));
    __half2 b0 = __floats2half2_rn(__ldg(p00 + 2), __ldg(p01 + 2));
    __half2 r1 = __floats2half2_rn(__ldg(p10 + 0), __ldg(p11 + 0));
    __half2 g1 = __floats2half2_rn(__ldg(p10 + 1), __ldg(p11 + 1));
    __half2 b1 = __floats2half2_rn(__ldg(p10 + 2), __ldg(p11 + 2));

    Quad q;
    q.u[0] = *(const unsigned*)&r0;
    q.u[1] = *(const unsigned*)&g0;
    q.u[2] = *(const unsigned*)&b0;
    q.u[3] = *(const unsigned*)&r1;
    q.u[4] = *(const unsigned*)&g1;
    q.u[5] = *(const unsigned*)&b1;
    q.u[6] = 0; q.u[7] = 0;
    g_quad[i] = q;
}

// 256-bit global load (sm_100+): 8 consecutive b32, 32B-aligned.
__device__ __forceinline__ void ldg256(const Quad* p, unsigned r[8]) {
    asm volatile("ld.global.nc.v8.b32 {%0,%1,%2,%3,%4,%5,%6,%7}, [%8];"
                 : "=r"(r[0]), "=r"(r[1]), "=r"(r[2]), "=r"(r[3]),
                   "=r"(r[4]), "=r"(r[5]), "=r"(r[6]), "=r"(r[7])
                 : "l"(p));
}

// ---------------------------------------------------------------------------
// Main: one thread per 4 consecutive pixels (12 floats = 3 aligned float4).
// Each block covers 1024 contiguous pixels of ONE image. Boxes computed
// in-block from the raw boxes input.
// ---------------------------------------------------------------------------
__global__ void __launch_bounds__(256)
paste_kernel(const float* __restrict__ img,
             const float* __restrict__ boxes,
             float* __restrict__ out) {
    __shared__ PBox sbox[NBX];
    int b = blockIdx.x >> 8;           // 256 blocks per image
    if (threadIdx.x < NBX) {
        const float* bx = boxes + ((size_t)b * NBX + threadIdx.x) * 4;
        float ymin = __ldg(bx + 0), xmin = __ldg(bx + 1);
        float ymax = __ldg(bx + 2), xmax = __ldg(bx + 3);
        float h = ymax - ymin;
        float w = xmax - xmin;
        float pw = h * SCALE_F;
        float ph = ASPECT_F * pw;
        float oy = ymin + h * 0.5f;
        float ox = xmin + w * 0.5f;
        float yp = fmaxf(oy - ph * 0.5f, 0.0f);
        float xp = fmaxf(ox - pw * 0.5f, 0.0f);
        if (yp + ph > (float)HH) yp = (float)HH - ph;
        if (xp + pw > (float)WW) xp = (float)WW - pw;
        PBox pb;
        pb.y0 = (int)yp;
        pb.x0 = (int)xp;
        pb.h  = (int)ph;
        pb.w  = (int)pw;
        pb.inv_h = (float)PNp / fmaxf((float)pb.h, 1.0f);
        pb.inv_w = (float)PNp / fmaxf((float)pb.w, 1.0f);
        pb.valid = (ph > MIN_PH_F) ? 1 : 0;
        pb.pad = 0;
        sbox[threadIdx.x] = pb;
    }
    __syncthreads();

    int t  = blockIdx.x * blockDim.x + threadIdx.x;
    int p0 = t << 2;                   // first pixel index of this group
    int rem = p0 & ((1 << 18) - 1);    // within-image index
    int y   = rem >> 9;                // W = 2^9
    int x   = rem & (WW - 1);

    // Find topmost covering box per pixel
    int cov[4] = {-1, -1, -1, -1};
    #pragma unroll
    for (int n = NBX - 1; n >= 0; --n) {
        PBox pb = sbox[n];
        if (!pb.valid) continue;
        int dy = y - pb.y0;
        if ((unsigned)dy >= (unsigned)pb.h) continue;
        int dx0 = x - pb.x0;
        #pragma unroll
        for (int k = 0; k < 4; ++k) {
            if (cov[k] < 0 && (unsigned)(dx0 + k) < (unsigned)pb.w) cov[k] = n;
        }
    }

    float px[4][3];
    bool allcov = (cov[0] >= 0) & (cov[1] >= 0) & (cov[2] >= 0) & (cov[3] >= 0);

    const float* ibase = img + (size_t)p0 * 3;
    if (!allcov) {
        float4 v0 = __ldcs((const float4*)(ibase + 0));
        float4 v1 = __ldcs((const float4*)(ibase + 4));
        float4 v2 = __ldcs((const float4*)(ibase + 8));
        px[0][0] = v0.x; px[0][1] = v0.y; px[0][2] = v0.z;
        px[1][0] = v0.w; px[1][1] = v1.x; px[1][2] = v1.y;
        px[2][0] = v1.z; px[2][1] = v1.w; px[2][2] = v2.x;
        px[3][0] = v2.y; px[3][1] = v2.z; px[3][2] = v2.w;
    }

    #pragma unroll
    for (int k = 0; k < 4; ++k) {
        if (cov[k] < 0) continue;
        PBox pb = sbox[cov[k]];
        int dy = y - pb.y0;
        int dx = (x + k) - pb.x0;

        float sy = ((float)dy + 0.5f) * pb.inv_h - 0.5f;
        float sx = ((float)dx + 0.5f) * pb.inv_w - 0.5f;
        sy = fminf(fmaxf(sy, 0.0f), (float)(PNp - 1));
        sx = fminf(fmaxf(sx, 0.0f), (float)(PNp - 1));

        int   yl = (int)floorf(sy);
        int   xl = (int)floorf(sx);
        float wy = sy - (float)yl;
        float wx = sx - (float)xl;

        unsigned q[8];
        ldg256(&g_quad[yl * PNp + xl], q);

        float2 r0 = __half22float2(*(const __half2*)&q[0]);  // (r00, r01)
        float2 g0 = __half22float2(*(const __half2*)&q[1]);
        float2 b0 = __half22float2(*(const __half2*)&q[2]);
        float2 r1 = __half22float2(*(const __half2*)&q[3]);  // (r10, r11)
        float2 g1 = __half22float2(*(const __half2*)&q[4]);
        float2 b1 = __half22float2(*(const __half2*)&q[5]);

        float omwy = 1.0f - wy;
        float omwx = 1.0f - wx;
        // y-interp (keeps xl/xh lanes), then x-interp
        float rlo = r0.x * omwy + r1.x * wy;
        float rhi = r0.y * omwy + r1.y * wy;
        float glo = g0.x * omwy + g1.x * wy;
        float ghi = g0.y * omwy + g1.y * wy;
        float blo = b0.x * omwy + b1.x * wy;
        float bhi = b0.y * omwy + b1.y * wy;
        px[k][0] = rlo * omwx + rhi * wx;
        px[k][1] = glo * omwx + ghi * wx;
        px[k][2] = blo * omwx + bhi * wx;
    }

    float4 o0, o1, o2;
    o0.x = px[0][0]; o0.y = px[0][1]; o0.z = px[0][2]; o0.w = px[1][0];
    o1.x = px[1][1]; o1.y = px[1][2]; o1.z = px[2][0]; o1.w = px[2][1];
    o2.x = px[2][2]; o2.y = px[3][0]; o2.z = px[3][1]; o2.w = px[3][2];

    float* obase = out + (size_t)p0 * 3;
    __stcs((float4*)(obase + 0), o0);
    __stcs((float4*)(obase + 4), o1);
    __stcs((float4*)(obase + 8), o2);
}

extern "C" void kernel_launch(void* const* d_in, const int* in_sizes, int n_in,
                              void* d_out, int out_size) {
    const float* images = (const float*)d_in[0];   // [32,512,512,3] f32
    const float* boxes  = (const float*)d_in[1];   // [32,6,4] f32
    const float* patch  = (const float*)d_in[2];   // [512,512,3] f32
    float* out = (float*)d_out;

    prep_patch_kernel<<<(PNp * PNp) / 256, 256>>>(patch);

    const int total = BB * HH * WW / 4;            // 2,097,152 threads
    paste_kernel<<<total / 256, 256>>>(images, boxes, out);
}